// round 1
// baseline (speedup 1.0000x reference)
#include <cuda_runtime.h>
#include <math.h>

// Problem constants
#define BS        128
#define N_PTS     32768
#define BASE      12
#define W         8.0f

#define RECON_FLOATS  (BS * N_PTS * 3)          // 12,582,912
#define RECON_VEC4    (RECON_FLOATS / 4)        // 3,145,728
#define NBLK_RECON    2048
#define NTHR_RECON    256

__device__ float g_partials[NBLK_RECON];

// ---------------------------------------------------------------------------
// Kernel 1: HBM-streaming partial sums of |pred_Recon - gt_Recon|
// ---------------------------------------------------------------------------
__global__ __launch_bounds__(NTHR_RECON)
void recon_partial_kernel(const float4* __restrict__ pred,
                          const float4* __restrict__ gt) {
    float s = 0.0f;
    int stride = gridDim.x * blockDim.x;                 // 524288
    for (int i = blockIdx.x * blockDim.x + threadIdx.x;
         i < RECON_VEC4; i += stride) {
        float4 a = pred[i];
        float4 b = gt[i];
        s += fabsf(a.x - b.x) + fabsf(a.y - b.y)
           + fabsf(a.z - b.z) + fabsf(a.w - b.w);
    }
    // warp reduce
    #pragma unroll
    for (int o = 16; o > 0; o >>= 1)
        s += __shfl_down_sync(0xFFFFFFFFu, s, o);
    __shared__ float sh[NTHR_RECON / 32];
    int lane = threadIdx.x & 31;
    int wid  = threadIdx.x >> 5;
    if (lane == 0) sh[wid] = s;
    __syncthreads();
    if (wid == 0) {
        s = (lane < NTHR_RECON / 32) ? sh[lane] : 0.0f;
        #pragma unroll
        for (int o = 4; o > 0; o >>= 1)
            s += __shfl_down_sync(0xFFFFFFFFu, s, o);
        if (lane == 0) g_partials[blockIdx.x] = s;
    }
}

// ---------------------------------------------------------------------------
// Kernel 2: finalize — small losses + combine partials, write 5 outputs
// ---------------------------------------------------------------------------
__global__ __launch_bounds__(256)
void finalize_kernel(const float* __restrict__ pred_Rot1,   // [BS,3]
                     const float* __restrict__ pred_Rot2,   // [BS,3]
                     const float* __restrict__ pred_Tran,   // [BS,3]
                     const float* __restrict__ pred_Size,   // [BS,3]
                     const float* __restrict__ gt_Rotation, // [BS,3,3]
                     const float* __restrict__ gt_Tran,     // [BS,3]
                     const float* __restrict__ gt_Size,     // [BS,3]
                     const int*   __restrict__ sym,         // [BS,6] int32
                     float* __restrict__ out) {             // [5]
    int t = threadIdx.x;

    float rot1_b = 0.0f, l2m_b = 0.0f, mask_b = 0.0f;
    float tran_b = 0.0f, size_b = 0.0f;

    if (t < BS) {
        const float* R = gt_Rotation + t * 9;     // row-major [3,3]
        // column 1 of R
        float c1x = R[0 * 3 + 1], c1y = R[1 * 3 + 1], c1z = R[2 * 3 + 1];
        float p1x = pred_Rot1[t * 3 + 0];
        float p1y = pred_Rot1[t * 3 + 1];
        float p1z = pred_Rot1[t * 3 + 2];
        float l10 = (fabsf(p1x - c1x) + fabsf(p1y - c1y) + fabsf(p1z - c1z)) * (1.0f / 3.0f);
        float l11 = (fabsf(p1x + c1x) + fabsf(p1y + c1y) + fabsf(p1z + c1z)) * (1.0f / 3.0f);
        rot1_b = (sym[t * 6 + 2] == 1) ? fminf(l10, l11) : l10;

        // columns 0 and 2 of R
        float c0x = R[0], c0y = R[3], c0z = R[6];
        float c2x = R[2], c2y = R[5], c2z = R[8];
        float p2x = pred_Rot2[t * 3 + 0];
        float p2y = pred_Rot2[t * 3 + 1];
        float p2z = pred_Rot2[t * 3 + 2];
        float lmin = 3.0e38f;
        #pragma unroll
        for (int k = 0; k < BASE; k++) {
            float theta = ((float)k / (float)BASE) * 6.283185307179586f;
            float ck = cosf(theta), sk = sinf(theta);
            float gx = ck * c0x - sk * c2x;
            float gy = ck * c0y - sk * c2y;
            float gz = ck * c0z - sk * c2z;
            float l = (fabsf(p2x - gx) + fabsf(p2y - gy) + fabsf(p2z - gz)) * (1.0f / 3.0f);
            lmin = fminf(lmin, l);
        }
        mask_b = (sym[t * 6 + 0] == 0) ? 1.0f : 0.0f;
        l2m_b = lmin * mask_b;

        #pragma unroll
        for (int i = 0; i < 3; i++) {
            tran_b += fabsf(pred_Tran[t * 3 + i] - gt_Tran[t * 3 + i]);
            size_b += fabsf(pred_Size[t * 3 + i] - gt_Size[t * 3 + i]);
        }
    }

    // all 256 threads: stride-sum recon partials
    float recon_b = 0.0f;
    for (int i = t; i < NBLK_RECON; i += 256)
        recon_b += g_partials[i];

    // block reductions (6 accumulators) via shared memory
    __shared__ float sh[6][256];
    sh[0][t] = rot1_b;
    sh[1][t] = l2m_b;
    sh[2][t] = mask_b;
    sh[3][t] = tran_b;
    sh[4][t] = size_b;
    sh[5][t] = recon_b;
    __syncthreads();
    for (int s = 128; s > 0; s >>= 1) {
        if (t < s) {
            #pragma unroll
            for (int q = 0; q < 6; q++)
                sh[q][t] += sh[q][t + s];
        }
        __syncthreads();
    }

    if (t == 0) {
        float rot1 = sh[0][0] / (float)BS;
        float valid = sh[2][0];
        float rot2 = (valid > 0.0f) ? sh[1][0] / fmaxf(valid, 1.0f) : 0.0f;
        float recon = sh[5][0] / (float)RECON_FLOATS;
        float tran  = sh[3][0] / (float)(BS * 3);
        float size  = sh[4][0] / (float)(BS * 3);
        out[0] = W * rot1;
        out[1] = W * rot2;
        out[2] = W * recon;
        out[3] = W * tran;
        out[4] = W * size;
    }
}

// ---------------------------------------------------------------------------
// Launch
// Input order (metadata): 0 pred_Rot1, 1 pred_Rot2, 2 pred_Recon, 3 pred_Tran,
//   4 pred_Size, 5 gt_Rotation, 6 gt_Recon, 7 gt_Tran, 8 gt_Size, 9 sym(int32)
// ---------------------------------------------------------------------------
extern "C" void kernel_launch(void* const* d_in, const int* in_sizes, int n_in,
                              void* d_out, int out_size) {
    const float* pred_Rot1  = (const float*)d_in[0];
    const float* pred_Rot2  = (const float*)d_in[1];
    const float* pred_Recon = (const float*)d_in[2];
    const float* pred_Tran  = (const float*)d_in[3];
    const float* pred_Size  = (const float*)d_in[4];
    const float* gt_Rotation= (const float*)d_in[5];
    const float* gt_Recon   = (const float*)d_in[6];
    const float* gt_Tran    = (const float*)d_in[7];
    const float* gt_Size    = (const float*)d_in[8];
    const int*   sym        = (const int*)d_in[9];
    float* out = (float*)d_out;

    recon_partial_kernel<<<NBLK_RECON, NTHR_RECON>>>(
        (const float4*)pred_Recon, (const float4*)gt_Recon);
    finalize_kernel<<<1, 256>>>(pred_Rot1, pred_Rot2, pred_Tran, pred_Size,
                                gt_Rotation, gt_Tran, gt_Size, sym, out);
}

// round 2
// speedup vs baseline: 1.0695x; 1.0695x over previous
#include <cuda_runtime.h>
#include <math.h>

// Problem constants
#define BS        128
#define N_PTS     32768
#define BASE      12
#define W         8.0f

#define RECON_FLOATS  (BS * N_PTS * 3)          // 12,582,912
#define RECON_VEC4    (RECON_FLOATS / 4)        // 3,145,728
#define NBLK          1024
#define NTHR          256
// 3,145,728 / (1024*256) = 12 float4 per thread exactly

__device__ float        g_partials[NBLK];
__device__ unsigned int g_counter = 0;

// cos/sin of 2*pi*k/12, k=0..11 (exact float values of cosf/sinf results)
__device__ __constant__ float COS_T[BASE] = {
     1.0f,  0.8660254037844387f,  0.5f,  0.0f, -0.5f, -0.8660254037844387f,
    -1.0f, -0.8660254037844387f, -0.5f,  0.0f,  0.5f,  0.8660254037844387f };
__device__ __constant__ float SIN_T[BASE] = {
     0.0f,  0.5f,  0.8660254037844387f,  1.0f,  0.8660254037844387f,  0.5f,
     0.0f, -0.5f, -0.8660254037844387f, -1.0f, -0.8660254037844387f, -0.5f };

__global__ __launch_bounds__(NTHR)
void fused_loss_kernel(const float4* __restrict__ predR,
                       const float4* __restrict__ gtR,
                       const float* __restrict__ pred_Rot1,   // [BS,3]
                       const float* __restrict__ pred_Rot2,   // [BS,3]
                       const float* __restrict__ pred_Tran,   // [BS,3]
                       const float* __restrict__ pred_Size,   // [BS,3]
                       const float* __restrict__ gt_Rotation, // [BS,3,3]
                       const float* __restrict__ gt_Tran,     // [BS,3]
                       const float* __restrict__ gt_Size,     // [BS,3]
                       const int*   __restrict__ sym,         // [BS,6] int32
                       float* __restrict__ out) {             // [5]
    const int t   = threadIdx.x;
    const int bid = blockIdx.x;

    // ---------------- streaming recon partial ----------------
    float s = 0.0f;
    int base = bid * NTHR + t;
    const int stride = NBLK * NTHR;   // 262144
    #pragma unroll
    for (int j = 0; j < RECON_VEC4 / (NBLK * NTHR); j++) {
        int i = base + j * stride;
        float4 a = predR[i];
        float4 b = gtR[i];
        s += fabsf(a.x - b.x) + fabsf(a.y - b.y)
           + fabsf(a.z - b.z) + fabsf(a.w - b.w);
    }
    // warp reduce
    #pragma unroll
    for (int o = 16; o > 0; o >>= 1)
        s += __shfl_down_sync(0xFFFFFFFFu, s, o);
    __shared__ float shw[NTHR / 32];
    int lane = t & 31, wid = t >> 5;
    if (lane == 0) shw[wid] = s;
    __syncthreads();
    __shared__ bool is_last;
    if (t == 0) {
        float bsum = 0.0f;
        #pragma unroll
        for (int q = 0; q < NTHR / 32; q++) bsum += shw[q];
        g_partials[bid] = bsum;
        __threadfence();
        unsigned int done = atomicAdd(&g_counter, 1u);
        is_last = (done == NBLK - 1);
    }
    __syncthreads();
    if (!is_last) return;

    // ---------------- last block: finalize ----------------
    float rot1_b = 0.0f, l2m_b = 0.0f, mask_b = 0.0f;
    float tran_b = 0.0f, size_b = 0.0f;

    if (t < BS) {
        const float* R = gt_Rotation + t * 9;     // row-major [3,3]
        float c1x = R[1], c1y = R[4], c1z = R[7];       // column 1
        float p1x = pred_Rot1[t * 3 + 0];
        float p1y = pred_Rot1[t * 3 + 1];
        float p1z = pred_Rot1[t * 3 + 2];
        float l10 = (fabsf(p1x - c1x) + fabsf(p1y - c1y) + fabsf(p1z - c1z)) * (1.0f / 3.0f);
        float l11 = (fabsf(p1x + c1x) + fabsf(p1y + c1y) + fabsf(p1z + c1z)) * (1.0f / 3.0f);
        rot1_b = (sym[t * 6 + 2] == 1) ? fminf(l10, l11) : l10;

        float c0x = R[0], c0y = R[3], c0z = R[6];       // column 0
        float c2x = R[2], c2y = R[5], c2z = R[8];       // column 2
        float p2x = pred_Rot2[t * 3 + 0];
        float p2y = pred_Rot2[t * 3 + 1];
        float p2z = pred_Rot2[t * 3 + 2];
        float lmin = 3.0e38f;
        #pragma unroll
        for (int k = 0; k < BASE; k++) {
            float ck = COS_T[k], sk = SIN_T[k];
            float gx = ck * c0x - sk * c2x;
            float gy = ck * c0y - sk * c2y;
            float gz = ck * c0z - sk * c2z;
            float l = (fabsf(p2x - gx) + fabsf(p2y - gy) + fabsf(p2z - gz)) * (1.0f / 3.0f);
            lmin = fminf(lmin, l);
        }
        mask_b = (sym[t * 6 + 0] == 0) ? 1.0f : 0.0f;
        l2m_b = lmin * mask_b;

        #pragma unroll
        for (int i = 0; i < 3; i++) {
            tran_b += fabsf(pred_Tran[t * 3 + i] - gt_Tran[t * 3 + i]);
            size_b += fabsf(pred_Size[t * 3 + i] - gt_Size[t * 3 + i]);
        }
    }

    // all 256 threads: stride-sum recon partials (deterministic order)
    float recon_b = 0.0f;
    #pragma unroll
    for (int j = 0; j < NBLK / NTHR; j++)
        recon_b += g_partials[t + j * NTHR];

    // block reduction of 6 accumulators
    __shared__ float sh[6][NTHR];
    sh[0][t] = rot1_b;
    sh[1][t] = l2m_b;
    sh[2][t] = mask_b;
    sh[3][t] = tran_b;
    sh[4][t] = size_b;
    sh[5][t] = recon_b;
    __syncthreads();
    for (int st = NTHR / 2; st > 0; st >>= 1) {
        if (t < st) {
            #pragma unroll
            for (int q = 0; q < 6; q++)
                sh[q][t] += sh[q][t + st];
        }
        __syncthreads();
    }

    if (t == 0) {
        float rot1  = sh[0][0] / (float)BS;
        float valid = sh[2][0];
        float rot2  = (valid > 0.0f) ? sh[1][0] / fmaxf(valid, 1.0f) : 0.0f;
        float recon = sh[5][0] / (float)RECON_FLOATS;
        float tran  = sh[3][0] / (float)(BS * 3);
        float size  = sh[4][0] / (float)(BS * 3);
        out[0] = W * rot1;
        out[1] = W * rot2;
        out[2] = W * recon;
        out[3] = W * tran;
        out[4] = W * size;
        g_counter = 0;   // reset for next (graph-replayed) call — deterministic
    }
}

// ---------------------------------------------------------------------------
// Launch. Input order: 0 pred_Rot1, 1 pred_Rot2, 2 pred_Recon, 3 pred_Tran,
//   4 pred_Size, 5 gt_Rotation, 6 gt_Recon, 7 gt_Tran, 8 gt_Size, 9 sym(int32)
// ---------------------------------------------------------------------------
extern "C" void kernel_launch(void* const* d_in, const int* in_sizes, int n_in,
                              void* d_out, int out_size) {
    fused_loss_kernel<<<NBLK, NTHR>>>(
        (const float4*)d_in[2], (const float4*)d_in[6],
        (const float*)d_in[0], (const float*)d_in[1],
        (const float*)d_in[3], (const float*)d_in[4],
        (const float*)d_in[5], (const float*)d_in[7],
        (const float*)d_in[8], (const int*)d_in[9],
        (float*)d_out);
}